// round 4
// baseline (speedup 1.0000x reference)
#include <cuda_runtime.h>

// out[b, s, d] = in[b, s, d] + PE[s, d]
// PE[s, 2i]   = sin(s / 10000^(2i/1024)),  PE[s, 2i+1] = cos(...)
//
// B=8, S=4096, D=1024, fp32 — 268 MB per launch.
// R3/R4 insight: effective LTS throughput (7.3 TB/s) already exceeds measured
// DRAM (5.9 TB/s) — the 134 MB input nearly fits in the 126 MB L2 and is
// re-read every graph replay. So: pin input in L2 (evict_last policy on
// loads), and keep the dead 134 MB output stream from thrashing it
// (evict_first policy on stores). DRAM then carries ~only the write stream.

#define SEQ_LEN 4096
#define D_MODEL 1024
#define BATCH   8
#define THREADS 256   // 256 threads * float4 = 1024 floats = one PE row

typedef unsigned long long u64;

__device__ __forceinline__ float4 ldg_L2_evict_last(const float4* p, u64 pol) {
    float4 v;
    asm volatile("ld.global.nc.L2::cache_hint.v4.f32 {%0,%1,%2,%3}, [%4], %5;"
                 : "=f"(v.x), "=f"(v.y), "=f"(v.z), "=f"(v.w)
                 : "l"(p), "l"(pol));
    return v;
}

__device__ __forceinline__ void stg_L2_evict_first(float4* p, float4 v, u64 pol) {
    asm volatile("st.global.L2::cache_hint.v4.f32 [%0], {%1,%2,%3,%4}, %5;"
                 :: "l"(p), "f"(v.x), "f"(v.y), "f"(v.z), "f"(v.w), "l"(pol)
                 : "memory");
}

__global__ void __launch_bounds__(THREADS, 8)
pe_add_kernel(const float4* __restrict__ in, float4* __restrict__ out) {
    const int pos = blockIdx.x;        // sequence position 0..4095
    const int t   = threadIdx.x;       // float4 index within row 0..255

    // L2 cache policies: input lines sticky, output lines disposable.
    u64 pol_last, pol_first;
    asm volatile("createpolicy.fractional.L2::evict_last.b64 %0, 1.0;"  : "=l"(pol_last));
    asm volatile("createpolicy.fractional.L2::evict_first.b64 %0, 1.0;" : "=l"(pol_first));

    // PE for this thread's float4 (dims 4t..4t+3), computed once, reused 8x.
    const float LOG2_10000 = 13.287712379549449f;
    const float fpos = (float)pos;

    float e0 = (float)(4 * t)     * (1.0f / 1024.0f);
    float e1 = (float)(4 * t + 2) * (1.0f / 1024.0f);
    float a0 = fpos / exp2f(e0 * LOG2_10000);
    float a1 = fpos / exp2f(e1 * LOG2_10000);

    float s0, c0, s1, c1;
    sincosf(a0, &s0, &c0);   // accurate variant: angles reach ~4095 rad
    sincosf(a1, &s1, &c1);

    const float4 pe = make_float4(s0, c0, s1, c1);

    // 32-bit element offsets in float4 units.
    const int row_f4       = D_MODEL / 4;            // 256
    const int batch_stride = SEQ_LEN * row_f4;       // 1,048,576
    int idx = pos * row_f4 + t;

    // 2-deep pipeline: next batch's load in flight while storing current.
    float4 cur = ldg_L2_evict_last(in + idx, pol_last);
#pragma unroll
    for (int b = 0; b < BATCH; ++b) {
        int next_idx = idx + batch_stride;
        float4 nxt;
        if (b < BATCH - 1) nxt = ldg_L2_evict_last(in + next_idx, pol_last);
        float4 v = cur;
        v.x += pe.x;
        v.y += pe.y;
        v.z += pe.z;
        v.w += pe.w;
        stg_L2_evict_first(out + idx, v, pol_first);
        cur = nxt;
        idx = next_idx;
    }
}

extern "C" void kernel_launch(void* const* d_in, const int* in_sizes, int n_in,
                              void* d_out, int out_size) {
    const float4* in  = (const float4*)d_in[0];
    float4*       out = (float4*)d_out;
    pe_add_kernel<<<SEQ_LEN, THREADS>>>(in, out);
}

// round 5
// speedup vs baseline: 1.0014x; 1.0014x over previous
#include <cuda_runtime.h>

// out[b, s, d] = in[b, s, d] + PE[s, d]
// PE[s, 2i]   = sin(s / 10000^(2i/1024)),  PE[s, 2i+1] = cos(...)
//
// B=8, S=4096, D=1024, fp32 — 268 MB per launch, re-run via graph replay.
// R5: deterministic partial L2 pin. R4 pinned 100% of the 134MB input in a
// 126MB L2 (oversubscribed -> thrash -> neutral). Now pin only batches 0-5
// (100.7MB, fits) with evict_last; stream batches 6-7 and ALL stores with
// evict_first so output transients can't displace the pinned set.
// Steady state DRAM/replay: ~34MB reads + 134MB writes instead of ~213MB.

#define SEQ_LEN 4096
#define D_MODEL 1024
#define BATCH   8
#define STICKY_BATCHES 6   // 6 * 16.78MB = 100.7MB pinned < 126MB L2
#define THREADS 256        // 256 threads * float4 = 1024 floats = one PE row

typedef unsigned long long u64;

__device__ __forceinline__ float4 ldg_pol(const float4* p, u64 pol) {
    float4 v;
    asm volatile("ld.global.nc.L2::cache_hint.v4.f32 {%0,%1,%2,%3}, [%4], %5;"
                 : "=f"(v.x), "=f"(v.y), "=f"(v.z), "=f"(v.w)
                 : "l"(p), "l"(pol));
    return v;
}

__device__ __forceinline__ void stg_pol(float4* p, float4 v, u64 pol) {
    asm volatile("st.global.L2::cache_hint.v4.f32 [%0], {%1,%2,%3,%4}, %5;"
                 :: "l"(p), "f"(v.x), "f"(v.y), "f"(v.z), "f"(v.w), "l"(pol)
                 : "memory");
}

__global__ void __launch_bounds__(THREADS, 8)
pe_add_kernel(const float4* __restrict__ in, float4* __restrict__ out) {
    const int pos = blockIdx.x;        // sequence position 0..4095
    const int t   = threadIdx.x;       // float4 index within row 0..255

    // Policies: pinned-input loads sticky; everything else disposable.
    u64 pol_last, pol_first;
    asm volatile("createpolicy.fractional.L2::evict_last.b64 %0, 1.0;"  : "=l"(pol_last));
    asm volatile("createpolicy.fractional.L2::evict_first.b64 %0, 1.0;" : "=l"(pol_first));

    // PE for this thread's float4 (dims 4t..4t+3), computed once, reused 8x.
    const float LOG2_10000 = 13.287712379549449f;
    const float fpos = (float)pos;

    float e0 = (float)(4 * t)     * (1.0f / 1024.0f);
    float e1 = (float)(4 * t + 2) * (1.0f / 1024.0f);
    float a0 = fpos / exp2f(e0 * LOG2_10000);
    float a1 = fpos / exp2f(e1 * LOG2_10000);

    float s0, c0, s1, c1;
    sincosf(a0, &s0, &c0);   // accurate variant: angles reach ~4095 rad
    sincosf(a1, &s1, &c1);

    const float4 pe = make_float4(s0, c0, s1, c1);

    // 32-bit element offsets in float4 units.
    const int row_f4       = D_MODEL / 4;            // 256
    const int batch_stride = SEQ_LEN * row_f4;       // 1,048,576
    int idx = pos * row_f4 + t;

    // 2-deep pipeline; per-batch compile-time policy selection.
    float4 cur = ldg_pol(in + idx, pol_last);        // batch 0 is sticky
#pragma unroll
    for (int b = 0; b < BATCH; ++b) {
        int next_idx = idx + batch_stride;
        float4 nxt;
        if (b < BATCH - 1) {
            u64 lp = (b + 1 < STICKY_BATCHES) ? pol_last : pol_first;
            nxt = ldg_pol(in + next_idx, lp);
        }
        float4 v = cur;
        v.x += pe.x;
        v.y += pe.y;
        v.z += pe.z;
        v.w += pe.w;
        stg_pol(out + idx, v, pol_first);
        cur = nxt;
        idx = next_idx;
    }
}

extern "C" void kernel_launch(void* const* d_in, const int* in_sizes, int n_in,
                              void* d_out, int out_size) {
    const float4* in  = (const float4*)d_in[0];
    float4*       out = (float4*)d_out;
    pe_add_kernel<<<SEQ_LEN, THREADS>>>(in, out);
}